// round 1
// baseline (speedup 1.0000x reference)
#include <cuda_runtime.h>
#include <math_constants.h>
#include <cstdint>

// Problem constants
#define S_LEN   2048
#define DMODEL  2048
#define NHEADS  16
#define HDIM    128
#define BATCH   4
#define MROWS   (BATCH * S_LEN)   // 8192

// ---------------------------------------------------------------------------
// Scratch (device globals; no allocation in kernel_launch)
// ---------------------------------------------------------------------------
__device__ float g_q[(size_t)BATCH * NHEADS * S_LEN * HDIM];   // [B,H,S,hd]
__device__ float g_k[(size_t)BATCH * NHEADS * S_LEN * HDIM];   // [B,H,S,hd]
__device__ float g_v[(size_t)BATCH * NHEADS * S_LEN * HDIM];   // [B,H,S,hd]
__device__ float g_att[(size_t)MROWS * DMODEL];                // [B,S,D]

// ---------------------------------------------------------------------------
// GEMM: out[m,n] = sum_k A[m,k] * W[n,k]   (both K-major)
// modes: 0 = Q (RoPE, ->g_q BHSD), 1 = K (RoPE, ->g_k BHSD),
//        2 = V (->g_v BHSD),       3 = A=g_att, ->Dout row-major
// ---------------------------------------------------------------------------
#define BM 128
#define BN 128
#define BK 16

__global__ __launch_bounds__(256, 2)
void gemm_kernel(const float* __restrict__ Ain, const float* __restrict__ W,
                 float* __restrict__ Dout, int mode)
{
    __shared__ float As[BK][BM];
    __shared__ float Bs[BK][BN];

    const float* A = (mode == 3) ? g_att : Ain;

    const int tid = threadIdx.x;
    const int tx = tid & 15;       // 0..15  (column group)
    const int ty = tid >> 4;       // 0..15  (row group)
    const int m0 = blockIdx.y * BM;
    const int n0 = blockIdx.x * BN;

    float acc[8][8] = {};

    for (int kt = 0; kt < DMODEL; kt += BK) {
        // load 128x16 A-tile and 128x16 W-tile (each 512 float4, 2 per thread)
        #pragma unroll
        for (int i = 0; i < 2; i++) {
            int f   = tid + i * 256;
            int row = f >> 2;
            int k4  = (f & 3) << 2;
            float4 a = *(const float4*)(A + (size_t)(m0 + row) * DMODEL + kt + k4);
            As[k4 + 0][row] = a.x; As[k4 + 1][row] = a.y;
            As[k4 + 2][row] = a.z; As[k4 + 3][row] = a.w;
            float4 b = *(const float4*)(W + (size_t)(n0 + row) * DMODEL + kt + k4);
            Bs[k4 + 0][row] = b.x; Bs[k4 + 1][row] = b.y;
            Bs[k4 + 2][row] = b.z; Bs[k4 + 3][row] = b.w;
        }
        __syncthreads();

        #pragma unroll
        for (int k = 0; k < BK; k++) {
            // rows: contiguous 8 (vectorized broadcast loads)
            float4 a0 = *(const float4*)&As[k][ty * 8];
            float4 a1 = *(const float4*)&As[k][ty * 8 + 4];
            float a[8] = {a0.x, a0.y, a0.z, a0.w, a1.x, a1.y, a1.z, a1.w};
            // cols: strided by 16 so d and d+64 land in the same thread (RoPE)
            float b[8];
            #pragma unroll
            for (int j = 0; j < 8; j++) b[j] = Bs[k][tx + 16 * j];
            #pragma unroll
            for (int i = 0; i < 8; i++)
                #pragma unroll
                for (int j = 0; j < 8; j++)
                    acc[i][j] = fmaf(a[i], b[j], acc[i][j]);
        }
        __syncthreads();
    }

    // ---------------- epilogue ----------------
    if (mode <= 1) {
        // RoPE + write [B,H,S,hd]. Tile width == head_dim, so h = n0/128,
        // local d = tx + 16*j. Pair (d, d+64) => (j, j+4).
        float* out = (mode == 0) ? g_q : g_k;
        const int h = n0 >> 7;
        float invf[4];
        #pragma unroll
        for (int j = 0; j < 4; j++) {
            int idx = tx + 16 * j;                       // 0..63
            invf[j] = (float)exp2(-(double)idx * 0.20762050593045952); // log2(1e4)/64
        }
        #pragma unroll
        for (int i = 0; i < 8; i++) {
            int m = m0 + ty * 8 + i;
            int b = m >> 11;           // /2048
            int s = m & 2047;
            float fs = (float)s;
            size_t base = (((size_t)b * NHEADS + h) * S_LEN + s) * HDIM;
            #pragma unroll
            for (int j = 0; j < 4; j++) {
                float th = fs * invf[j];
                float c, sn;
                sincosf(th, &sn, &c);
                float lo = acc[i][j], hi = acc[i][j + 4];
                out[base + tx + 16 * j]      = lo * c - hi * sn;
                out[base + tx + 16 * j + 64] = hi * c + lo * sn;
            }
        }
    } else if (mode == 2) {
        const int h = n0 >> 7;
        #pragma unroll
        for (int i = 0; i < 8; i++) {
            int m = m0 + ty * 8 + i;
            int b = m >> 11;
            int s = m & 2047;
            size_t base = (((size_t)b * NHEADS + h) * S_LEN + s) * HDIM;
            #pragma unroll
            for (int j = 0; j < 8; j++)
                g_v[base + tx + 16 * j] = acc[i][j];
        }
    } else {
        #pragma unroll
        for (int i = 0; i < 8; i++) {
            int m = m0 + ty * 8 + i;
            #pragma unroll
            for (int j = 0; j < 8; j++)
                Dout[(size_t)m * DMODEL + n0 + tx + 16 * j] = acc[i][j];
        }
    }
}

// ---------------------------------------------------------------------------
// Flash attention (causal), fp32. BM=128 query rows, BN=64 key rows per tile.
// 256 threads (16x16). Per thread: scores 8x4, output 8x8.
// ---------------------------------------------------------------------------
#define FA_BM 128
#define FA_BN 64
#define KS_STRIDE 129
#define PS_STRIDE 129
#define FA_SMEM ((FA_BM * HDIM + FA_BN * KS_STRIDE + FA_BN * HDIM + FA_BN * PS_STRIDE) * 4)

__global__ __launch_bounds__(256, 1)
void flash_kernel()
{
    extern __shared__ float sm[];
    float* Qs = sm;                            // [128][128]
    float* Ks = Qs + FA_BM * HDIM;             // [64][129]
    float* Vs = Ks + FA_BN * KS_STRIDE;        // [64][128]
    float* Ps = Vs + FA_BN * HDIM;             // [64][129]  (P transposed: [key][row])

    const int tid = threadIdx.x;
    const int tx = tid & 15;
    const int ty = tid >> 4;
    const int qt = blockIdx.x;
    const int bh = blockIdx.y;

    const float* qbase = g_q + (size_t)bh * S_LEN * HDIM;
    const float* kbase = g_k + (size_t)bh * S_LEN * HDIM;
    const float* vbase = g_v + (size_t)bh * S_LEN * HDIM;

    // load Q tile (128x128): 4096 float4, 16 per thread, fully coalesced
    #pragma unroll
    for (int i = 0; i < 16; i++) {
        int f  = tid + i * 256;
        int r  = f >> 5;
        int c4 = (f & 31) << 2;
        *(float4*)(Qs + r * HDIM + c4) =
            *(const float4*)(qbase + (size_t)(qt * FA_BM + r) * HDIM + c4);
    }

    float o[8][8] = {};
    float mi[8], li[8];
    #pragma unroll
    for (int i = 0; i < 8; i++) { mi[i] = -CUDART_INF_F; li[i] = 0.f; }

    const int nkt = 2 * qt + 2;
    const float scale = 0.08838834764831845f;   // 1/sqrt(128)

    for (int kt = 0; kt < nkt; kt++) {
        __syncthreads();  // prev PV done (Vs/Ps), Q visible on first iter

        // load K and V tiles (64x128 each)
        #pragma unroll
        for (int i = 0; i < 8; i++) {
            int f  = tid + i * 256;
            int r  = f >> 5;
            int c4 = (f & 31) << 2;
            float4 kv = *(const float4*)(kbase + (size_t)(kt * FA_BN + r) * HDIM + c4);
            float* kd = Ks + r * KS_STRIDE + c4;
            kd[0] = kv.x; kd[1] = kv.y; kd[2] = kv.z; kd[3] = kv.w;
            *(float4*)(Vs + r * HDIM + c4) =
                *(const float4*)(vbase + (size_t)(kt * FA_BN + r) * HDIM + c4);
        }
        __syncthreads();

        // scores: rows 8*ty+i, cols 4*tx+j
        float sc[8][4] = {};
        #pragma unroll 4
        for (int d = 0; d < HDIM; d++) {
            float qv[8], kv[4];
            #pragma unroll
            for (int i = 0; i < 8; i++) qv[i] = Qs[(ty * 8 + i) * HDIM + d];
            #pragma unroll
            for (int j = 0; j < 4; j++) kv[j] = Ks[(tx * 4 + j) * KS_STRIDE + d];
            #pragma unroll
            for (int i = 0; i < 8; i++)
                #pragma unroll
                for (int j = 0; j < 4; j++)
                    sc[i][j] = fmaf(qv[i], kv[j], sc[i][j]);
        }

        const bool needmask = (kt >= 2 * qt);

        // online softmax (row groups of 16 tx-lanes; shfl-xor within 16)
        #pragma unroll
        for (int i = 0; i < 8; i++) {
            int r_glob = qt * FA_BM + ty * 8 + i;
            float mx = -CUDART_INF_F;
            #pragma unroll
            for (int j = 0; j < 4; j++) {
                float v = sc[i][j] * scale;
                if (needmask) {
                    int c_glob = kt * FA_BN + tx * 4 + j;
                    if (c_glob > r_glob) v = -CUDART_INF_F;
                }
                sc[i][j] = v;
                mx = fmaxf(mx, v);
            }
            #pragma unroll
            for (int off = 8; off; off >>= 1)
                mx = fmaxf(mx, __shfl_xor_sync(0xffffffffu, mx, off));
            float mnew = fmaxf(mi[i], mx);
            float fct  = __expf(mi[i] - mnew);
            mi[i] = mnew;
            float ssum = 0.f;
            #pragma unroll
            for (int j = 0; j < 4; j++) {
                float p = __expf(sc[i][j] - mnew);
                ssum += p;
                Ps[(tx * 4 + j) * PS_STRIDE + ty * 8 + i] = p;
            }
            #pragma unroll
            for (int off = 8; off; off >>= 1)
                ssum += __shfl_xor_sync(0xffffffffu, ssum, off);
            li[i] = li[i] * fct + ssum;
            #pragma unroll
            for (int j = 0; j < 8; j++) o[i][j] *= fct;
        }
        __syncthreads();

        // O += P @ V : rows 8*ty+i, cols 8*tx+j
        #pragma unroll 2
        for (int kk = 0; kk < FA_BN; kk++) {
            float pv[8];
            #pragma unroll
            for (int i = 0; i < 8; i++) pv[i] = Ps[kk * PS_STRIDE + ty * 8 + i];
            float4 v0 = *(const float4*)(Vs + kk * HDIM + tx * 8);
            float4 v1 = *(const float4*)(Vs + kk * HDIM + tx * 8 + 4);
            float vv[8] = {v0.x, v0.y, v0.z, v0.w, v1.x, v1.y, v1.z, v1.w};
            #pragma unroll
            for (int i = 0; i < 8; i++)
                #pragma unroll
                for (int j = 0; j < 8; j++)
                    o[i][j] = fmaf(pv[i], vv[j], o[i][j]);
        }
    }

    // epilogue: normalize and write [B,S,D]
    const int b = bh >> 4;
    const int h = bh & 15;
    #pragma unroll
    for (int i = 0; i < 8; i++) {
        float inv = 1.0f / li[i];
        int s = qt * FA_BM + ty * 8 + i;
        float* dst = g_att + ((size_t)b * S_LEN + s) * DMODEL + h * HDIM + tx * 8;
        float4 w0 = make_float4(o[i][0] * inv, o[i][1] * inv, o[i][2] * inv, o[i][3] * inv);
        float4 w1 = make_float4(o[i][4] * inv, o[i][5] * inv, o[i][6] * inv, o[i][7] * inv);
        *(float4*)(dst)     = w0;
        *(float4*)(dst + 4) = w1;
    }
}

// ---------------------------------------------------------------------------
// Launch
// ---------------------------------------------------------------------------
extern "C" void kernel_launch(void* const* d_in, const int* in_sizes, int n_in,
                              void* d_out, int out_size)
{
    const float* x  = (const float*)d_in[0];
    const float* Wq = (const float*)d_in[1];
    const float* Wk = (const float*)d_in[2];
    const float* Wv = (const float*)d_in[3];
    const float* Wo = (const float*)d_in[4];
    float* out = (float*)d_out;

    dim3 gblk(DMODEL / BN, MROWS / BM);   // 16 x 64

    gemm_kernel<<<gblk, 256>>>(x, Wq, nullptr, 0);   // Q + RoPE
    gemm_kernel<<<gblk, 256>>>(x, Wk, nullptr, 1);   // K + RoPE
    gemm_kernel<<<gblk, 256>>>(x, Wv, nullptr, 2);   // V

    cudaFuncSetAttribute(flash_kernel,
                         cudaFuncAttributeMaxDynamicSharedMemorySize, FA_SMEM);
    flash_kernel<<<dim3(S_LEN / FA_BM, BATCH * NHEADS), 256, FA_SMEM>>>();

    gemm_kernel<<<gblk, 256>>>(nullptr, Wo, out, 3); // output projection
}

// round 3
// speedup vs baseline: 2.0423x; 2.0423x over previous
#include <cuda_runtime.h>
#include <cuda_bf16.h>
#include <math_constants.h>
#include <cstdint>

// Problem constants
#define S_LEN   2048
#define DMODEL  2048
#define NHEADS  16
#define HDIM    128
#define BATCH   4
#define MROWS   (BATCH * S_LEN)   // 8192

// ---------------------------------------------------------------------------
// Scratch (device globals; no allocation in kernel_launch)
// ---------------------------------------------------------------------------
__device__ __nv_bfloat16 g_xhi[(size_t)MROWS * DMODEL];
__device__ __nv_bfloat16 g_xlo[(size_t)MROWS * DMODEL];
__device__ __nv_bfloat16 g_whi[4][(size_t)DMODEL * DMODEL];
__device__ __nv_bfloat16 g_wlo[4][(size_t)DMODEL * DMODEL];
__device__ float g_q[(size_t)BATCH * NHEADS * S_LEN * HDIM];   // [B,H,S,hd]
__device__ float g_k[(size_t)BATCH * NHEADS * S_LEN * HDIM];
__device__ float g_v[(size_t)BATCH * NHEADS * S_LEN * HDIM];
__device__ __nv_bfloat16 g_atthi[(size_t)MROWS * DMODEL];      // [B,S,D]
__device__ __nv_bfloat16 g_attlo[(size_t)MROWS * DMODEL];
__device__ float g_ct[64 * S_LEN];                              // cos[d][s]
__device__ float g_st[64 * S_LEN];                              // sin[d][s]

// ---------------------------------------------------------------------------
// PTX helpers (baseline features only: sm_80-class, compile on sm_103)
// ---------------------------------------------------------------------------
__device__ __forceinline__ void cp16(uint32_t smem_dst, const void* gptr) {
    asm volatile("cp.async.cg.shared.global [%0], [%1], 16;"
                 :: "r"(smem_dst), "l"(__cvta_generic_to_global(gptr)) : "memory");
}
__device__ __forceinline__ void cp_commit() {
    asm volatile("cp.async.commit_group;" ::: "memory");
}
template <int N>
__device__ __forceinline__ void cp_wait() {
    asm volatile("cp.async.wait_group %0;" :: "n"(N) : "memory");
}
__device__ __forceinline__ void ldsm4(uint32_t addr, uint32_t r[4]) {
    asm volatile("ldmatrix.sync.aligned.m8n8.x4.shared.b16 {%0,%1,%2,%3}, [%4];"
                 : "=r"(r[0]), "=r"(r[1]), "=r"(r[2]), "=r"(r[3]) : "r"(addr));
}
__device__ __forceinline__ void mma16816(float c[4], const uint32_t a[4],
                                         const uint32_t b0, const uint32_t b1) {
    asm volatile(
        "mma.sync.aligned.m16n8k16.row.col.f32.bf16.bf16.f32 "
        "{%0,%1,%2,%3}, {%4,%5,%6,%7}, {%8,%9}, {%0,%1,%2,%3};"
        : "+f"(c[0]), "+f"(c[1]), "+f"(c[2]), "+f"(c[3])
        : "r"(a[0]), "r"(a[1]), "r"(a[2]), "r"(a[3]), "r"(b0), "r"(b1));
}

// ---------------------------------------------------------------------------
// Split fp32 -> bf16 (hi, lo).  which: 0 = x, 1..4 = Wq,Wk,Wv,Wo
// ---------------------------------------------------------------------------
__global__ void split_kernel(const float4* __restrict__ src, int which, int n4)
{
    __nv_bfloat16 *hi, *lo;
    if (which == 0) { hi = g_xhi; lo = g_xlo; }
    else            { hi = g_whi[which - 1]; lo = g_wlo[which - 1]; }

    for (int i = blockIdx.x * blockDim.x + threadIdx.x; i < n4;
         i += gridDim.x * blockDim.x) {
        float4 v = src[i];
        float f[4] = {v.x, v.y, v.z, v.w};
        __nv_bfloat16 h[4], l[4];
        #pragma unroll
        for (int j = 0; j < 4; j++) {
            h[j] = __float2bfloat16(f[j]);
            l[j] = __float2bfloat16(f[j] - __bfloat162float(h[j]));
        }
        __nv_bfloat162* hp = reinterpret_cast<__nv_bfloat162*>(hi + 4 * (size_t)i);
        __nv_bfloat162* lp = reinterpret_cast<__nv_bfloat162*>(lo + 4 * (size_t)i);
        hp[0] = __halves2bfloat162(h[0], h[1]);
        hp[1] = __halves2bfloat162(h[2], h[3]);
        lp[0] = __halves2bfloat162(l[0], l[1]);
        lp[1] = __halves2bfloat162(l[2], l[3]);
    }
}

// ---------------------------------------------------------------------------
// RoPE cos/sin tables: g_ct[d*2048+s], d in [0,64)
// ---------------------------------------------------------------------------
__global__ void rope_tab_kernel()
{
    int i = blockIdx.x * blockDim.x + threadIdx.x;
    if (i >= 64 * S_LEN) return;
    int d = i >> 11, s = i & 2047;
    float invf = (float)exp2(-(double)d * 0.20762050593045952);  // log2(1e4)/64
    float th = (float)s * invf;
    float c, sn;
    sincosf(th, &sn, &c);
    g_ct[i] = c;
    g_st[i] = sn;
}

// ---------------------------------------------------------------------------
// RoPE in-place over g_q, g_k  ([B,H,S,hd], pair (d, d+64))
// ---------------------------------------------------------------------------
__global__ void rope_apply_kernel()
{
    const int total = BATCH * NHEADS * S_LEN * 64;
    int i = blockIdx.x * blockDim.x + threadIdx.x;
    if (i >= total) return;
    int d = i & 63;
    int rs = i >> 6;            // flat (b,h,s)
    int s = rs & 2047;
    size_t base = (size_t)rs * HDIM;
    float c  = g_ct[d * S_LEN + s];
    float sn = g_st[d * S_LEN + s];

    float qlo = g_q[base + d], qhi = g_q[base + d + 64];
    g_q[base + d]      = qlo * c - qhi * sn;
    g_q[base + d + 64] = qhi * c + qlo * sn;

    float klo = g_k[base + d], khi = g_k[base + d + 64];
    g_k[base + d]      = klo * c - khi * sn;
    g_k[base + d + 64] = khi * c + klo * sn;
}

// ---------------------------------------------------------------------------
// HMMA GEMM: D[m,n] = sum_k A[m,k]*W[n,k] via 3-product bf16 split.
// Block 128x128, BK=64, 8 warps (2m x 4n), warp tile 64x32, mma.m16n8k16.
// modes: 0=Q(->g_q raw) 1=K(->g_k raw) 2=V(->g_v) 3=att@Wo -> Dout
// ---------------------------------------------------------------------------
#define GM_BM 128
#define GM_BN 128
#define GM_BK 64
#define GM_NIT (DMODEL / GM_BK)          // 32
#define GM_ARR 16384                     // one 128x64 bf16 array
#define GM_STAGE (4 * GM_ARR)            // Ahi,Alo,Bhi,Blo = 64KB
#define GM_SMEM (2 * GM_STAGE)           // 128KB

__device__ __forceinline__ void gm_load_stage(
    uint32_t t0, int kt, int m0, int n0, int tid,
    const __nv_bfloat16* __restrict__ Ah, const __nv_bfloat16* __restrict__ Al,
    const __nv_bfloat16* __restrict__ Bh, const __nv_bfloat16* __restrict__ Bl)
{
    const int k0 = kt * GM_BK;
    #pragma unroll
    for (int i = 0; i < 4; i++) {
        int lin = tid + i * 256;
        int row = lin >> 3, ch = lin & 7;
        uint32_t soff = (uint32_t)(row * 128 + ((ch ^ (row & 7)) << 4));
        size_t ga = (size_t)(m0 + row) * DMODEL + k0 + ch * 8;
        size_t gb = (size_t)(n0 + row) * DMODEL + k0 + ch * 8;
        cp16(t0 + soff,              Ah + ga);
        cp16(t0 + GM_ARR + soff,     Al + ga);
        cp16(t0 + 2 * GM_ARR + soff, Bh + gb);
        cp16(t0 + 3 * GM_ARR + soff, Bl + gb);
    }
}

__global__ __launch_bounds__(256, 1)
void gemm_hmma(float* __restrict__ Dout, int mode)
{
    extern __shared__ char smraw[];
    const uint32_t sbase = (uint32_t)__cvta_generic_to_shared(smraw);
    const int tid  = threadIdx.x;
    const int warp = tid >> 5;
    const int lane = tid & 31;
    const int m0 = blockIdx.y * GM_BM;
    const int n0 = blockIdx.x * GM_BN;

    const __nv_bfloat16 *Ah, *Al;
    if (mode == 3) { Ah = g_atthi; Al = g_attlo; }
    else           { Ah = g_xhi;   Al = g_xlo; }
    const __nv_bfloat16* Bh = g_whi[mode];
    const __nv_bfloat16* Bl = g_wlo[mode];

    // warp layout: 2 (m) x 4 (n); warp tile 64x32
    const int wm = warp & 1;
    const int wn = warp >> 1;
    const int quad = lane >> 3;
    const int lr   = lane & 7;

    // ldmatrix lane rows (A: x4 over m16 x k16; B: x4 over two n8 tiles x k16)
    int arow[4], brow[2];
    #pragma unroll
    for (int i = 0; i < 4; i++) arow[i] = wm * 64 + i * 16 + (quad & 1) * 8 + lr;
    const int aqp = quad >> 1;
    #pragma unroll
    for (int j = 0; j < 2; j++) brow[j] = wn * 32 + j * 16 + (quad >> 1) * 8 + lr;
    const int bqp = quad & 1;

    float c[4][4][4];
    #pragma unroll
    for (int i = 0; i < 4; i++)
        #pragma unroll
        for (int j = 0; j < 4; j++)
            #pragma unroll
            for (int e = 0; e < 4; e++) c[i][j][e] = 0.f;

    gm_load_stage(sbase, 0, m0, n0, tid, Ah, Al, Bh, Bl);
    cp_commit();

    #pragma unroll 1
    for (int kt = 0; kt < GM_NIT; kt++) {
        if (kt + 1 < GM_NIT) {
            gm_load_stage(sbase + ((kt + 1) & 1) * GM_STAGE, kt + 1, m0, n0, tid,
                          Ah, Al, Bh, Bl);
            cp_commit();
            cp_wait<1>();
        } else {
            cp_wait<0>();
        }
        __syncthreads();

        const uint32_t t0 = sbase + (kt & 1) * GM_STAGE;
        #pragma unroll
        for (int s = 0; s < 4; s++) {
            uint32_t ah[4][4], al[4][4];
            #pragma unroll
            for (int i = 0; i < 4; i++) {
                uint32_t off = (uint32_t)(arow[i] * 128 +
                               (((s * 2 + aqp) ^ (arow[i] & 7)) << 4));
                ldsm4(t0 + off,          ah[i]);
                ldsm4(t0 + GM_ARR + off, al[i]);
            }
            uint32_t bh[4][2], bl[4][2];
            #pragma unroll
            for (int j2 = 0; j2 < 2; j2++) {
                uint32_t off = (uint32_t)(brow[j2] * 128 +
                               (((s * 2 + bqp) ^ (brow[j2] & 7)) << 4));
                uint32_t t[4];
                ldsm4(t0 + 2 * GM_ARR + off, t);
                bh[2*j2][0] = t[0]; bh[2*j2][1] = t[1];
                bh[2*j2+1][0] = t[2]; bh[2*j2+1][1] = t[3];
                ldsm4(t0 + 3 * GM_ARR + off, t);
                bl[2*j2][0] = t[0]; bl[2*j2][1] = t[1];
                bl[2*j2+1][0] = t[2]; bl[2*j2+1][1] = t[3];
            }
            #pragma unroll
            for (int i = 0; i < 4; i++)
                #pragma unroll
                for (int j = 0; j < 4; j++) {
                    mma16816(c[i][j], ah[i], bh[j][0], bh[j][1]);
                    mma16816(c[i][j], al[i], bh[j][0], bh[j][1]);
                    mma16816(c[i][j], ah[i], bl[j][0], bl[j][1]);
                }
        }
        __syncthreads();
    }

    // ---------------- epilogue ----------------
    const int h = n0 >> 7;   // BN == HDIM: one head per CTA column
    float* outp = (mode == 0) ? g_q : (mode == 1) ? g_k : g_v;

    #pragma unroll
    for (int i = 0; i < 4; i++) {
        int r0 = m0 + wm * 64 + i * 16 + (lane >> 2);
        #pragma unroll
        for (int half = 0; half < 2; half++) {
            int r = r0 + half * 8;
            #pragma unroll
            for (int j = 0; j < 4; j++) {
                int d = wn * 32 + j * 8 + (lane & 3) * 2;
                float2 v2 = make_float2(c[i][j][half * 2], c[i][j][half * 2 + 1]);
                if (mode <= 2) {
                    int bb = r >> 11, ss = r & 2047;
                    size_t base = (((size_t)bb * NHEADS + h) * S_LEN + ss) * HDIM + d;
                    *(float2*)(outp + base) = v2;
                } else {
                    *(float2*)(Dout + (size_t)r * DMODEL + n0 + d) = v2;
                }
            }
        }
    }
}

// ---------------------------------------------------------------------------
// Flash attention (causal), fp32 SIMT.  Emits bf16 hi/lo att for Wo GEMM.
// ---------------------------------------------------------------------------
#define FA_BM 128
#define FA_BN 64
#define KS_STRIDE 129
#define PS_STRIDE 129
#define FA_SMEM ((FA_BM * HDIM + FA_BN * KS_STRIDE + FA_BN * HDIM + FA_BN * PS_STRIDE) * 4)

__global__ __launch_bounds__(256, 1)
void flash_kernel()
{
    extern __shared__ float smf[];
    float* Qs = smf;
    float* Ks = Qs + FA_BM * HDIM;
    float* Vs = Ks + FA_BN * KS_STRIDE;
    float* Ps = Vs + FA_BN * HDIM;

    const int tid = threadIdx.x;
    const int tx = tid & 15;
    const int ty = tid >> 4;
    const int qt = blockIdx.x;
    const int bh = blockIdx.y;

    const float* qbase = g_q + (size_t)bh * S_LEN * HDIM;
    const float* kbase = g_k + (size_t)bh * S_LEN * HDIM;
    const float* vbase = g_v + (size_t)bh * S_LEN * HDIM;

    #pragma unroll
    for (int i = 0; i < 16; i++) {
        int f  = tid + i * 256;
        int r  = f >> 5;
        int c4 = (f & 31) << 2;
        *(float4*)(Qs + r * HDIM + c4) =
            *(const float4*)(qbase + (size_t)(qt * FA_BM + r) * HDIM + c4);
    }

    float o[8][8] = {};
    float mi[8], li[8];
    #pragma unroll
    for (int i = 0; i < 8; i++) { mi[i] = -CUDART_INF_F; li[i] = 0.f; }

    const int nkt = 2 * qt + 2;
    const float scale = 0.08838834764831845f;

    for (int kt = 0; kt < nkt; kt++) {
        __syncthreads();
        #pragma unroll
        for (int i = 0; i < 8; i++) {
            int f  = tid + i * 256;
            int r  = f >> 5;
            int c4 = (f & 31) << 2;
            float4 kv = *(const float4*)(kbase + (size_t)(kt * FA_BN + r) * HDIM + c4);
            float* kd = Ks + r * KS_STRIDE + c4;
            kd[0] = kv.x; kd[1] = kv.y; kd[2] = kv.z; kd[3] = kv.w;
            *(float4*)(Vs + r * HDIM + c4) =
                *(const float4*)(vbase + (size_t)(kt * FA_BN + r) * HDIM + c4);
        }
        __syncthreads();

        float sc[8][4] = {};
        #pragma unroll 4
        for (int d = 0; d < HDIM; d++) {
            float qv[8], kv[4];
            #pragma unroll
            for (int i = 0; i < 8; i++) qv[i] = Qs[(ty * 8 + i) * HDIM + d];
            #pragma unroll
            for (int j = 0; j < 4; j++) kv[j] = Ks[(tx * 4 + j) * KS_STRIDE + d];
            #pragma unroll
            for (int i = 0; i < 8; i++)
                #pragma unroll
                for (int j = 0; j < 4; j++)
                    sc[i][j] = fmaf(qv[i], kv[j], sc[i][j]);
        }

        const bool needmask = (kt >= 2 * qt);

        #pragma unroll
        for (int i = 0; i < 8; i++) {
            int r_glob = qt * FA_BM + ty * 8 + i;
            float mx = -CUDART_INF_F;
            #pragma unroll
            for (int j = 0; j < 4; j++) {
                float v = sc[i][j] * scale;
                if (needmask) {
                    int c_glob = kt * FA_BN + tx * 4 + j;
                    if (c_glob > r_glob) v = -CUDART_INF_F;
                }
                sc[i][j] = v;
                mx = fmaxf(mx, v);
            }
            #pragma unroll
            for (int off = 8; off; off >>= 1)
                mx = fmaxf(mx, __shfl_xor_sync(0xffffffffu, mx, off));
            float mnew = fmaxf(mi[i], mx);
            float fct  = __expf(mi[i] - mnew);
            mi[i] = mnew;
            float ssum = 0.f;
            #pragma unroll
            for (int j = 0; j < 4; j++) {
                float p = __expf(sc[i][j] - mnew);
                ssum += p;
                Ps[(tx * 4 + j) * PS_STRIDE + ty * 8 + i] = p;
            }
            #pragma unroll
            for (int off = 8; off; off >>= 1)
                ssum += __shfl_xor_sync(0xffffffffu, ssum, off);
            li[i] = li[i] * fct + ssum;
            #pragma unroll
            for (int j = 0; j < 8; j++) o[i][j] *= fct;
        }
        __syncthreads();

        #pragma unroll 2
        for (int kk = 0; kk < FA_BN; kk++) {
            float pv[8];
            #pragma unroll
            for (int i = 0; i < 8; i++) pv[i] = Ps[kk * PS_STRIDE + ty * 8 + i];
            float4 v0 = *(const float4*)(Vs + kk * HDIM + tx * 8);
            float4 v1 = *(const float4*)(Vs + kk * HDIM + tx * 8 + 4);
            float vv[8] = {v0.x, v0.y, v0.z, v0.w, v1.x, v1.y, v1.z, v1.w};
            #pragma unroll
            for (int i = 0; i < 8; i++)
                #pragma unroll
                for (int j = 0; j < 8; j++)
                    o[i][j] = fmaf(pv[i], vv[j], o[i][j]);
        }
    }

    // epilogue: normalize and write bf16 hi/lo att [B,S,D]
    const int b = bh >> 4;
    const int h = bh & 15;
    #pragma unroll
    for (int i = 0; i < 8; i++) {
        float inv = 1.0f / li[i];
        int s = qt * FA_BM + ty * 8 + i;
        size_t base = ((size_t)b * S_LEN + s) * DMODEL + h * HDIM + tx * 8;
        __nv_bfloat16 hh[8], ll[8];
        #pragma unroll
        for (int j = 0; j < 8; j++) {
            float val = o[i][j] * inv;
            hh[j] = __float2bfloat16(val);
            ll[j] = __float2bfloat16(val - __bfloat162float(hh[j]));
        }
        *(uint4*)(g_atthi + base) = *(uint4*)hh;
        *(uint4*)(g_attlo + base) = *(uint4*)ll;
    }
}

// ---------------------------------------------------------------------------
// Launch
// ---------------------------------------------------------------------------
extern "C" void kernel_launch(void* const* d_in, const int* in_sizes, int n_in,
                              void* d_out, int out_size)
{
    const float* x  = (const float*)d_in[0];
    const float* Wq = (const float*)d_in[1];
    const float* Wk = (const float*)d_in[2];
    const float* Wv = (const float*)d_in[3];
    const float* Wo = (const float*)d_in[4];
    float* out = (float*)d_out;

    int n4x = MROWS * DMODEL / 4;
    int n4w = DMODEL * DMODEL / 4;
    split_kernel<<<2048, 256>>>((const float4*)x,  0, n4x);
    split_kernel<<<1024, 256>>>((const float4*)Wq, 1, n4w);
    split_kernel<<<1024, 256>>>((const float4*)Wk, 2, n4w);
    split_kernel<<<1024, 256>>>((const float4*)Wv, 3, n4w);
    split_kernel<<<1024, 256>>>((const float4*)Wo, 4, n4w);
    rope_tab_kernel<<<(64 * S_LEN + 255) / 256, 256>>>();

    cudaFuncSetAttribute(gemm_hmma, cudaFuncAttributeMaxDynamicSharedMemorySize, GM_SMEM);
    dim3 gblk(DMODEL / GM_BN, MROWS / GM_BM);   // 16 x 64

    gemm_hmma<<<gblk, 256, GM_SMEM>>>(nullptr, 0);   // Q (raw)
    gemm_hmma<<<gblk, 256, GM_SMEM>>>(nullptr, 1);   // K (raw)
    gemm_hmma<<<gblk, 256, GM_SMEM>>>(nullptr, 2);   // V

    rope_apply_kernel<<<(BATCH * NHEADS * S_LEN * 64 + 255) / 256, 256>>>();

    cudaFuncSetAttribute(flash_kernel,
                         cudaFuncAttributeMaxDynamicSharedMemorySize, FA_SMEM);
    flash_kernel<<<dim3(S_LEN / FA_BM, BATCH * NHEADS), 256, FA_SMEM>>>();

    gemm_hmma<<<gblk, 256, GM_SMEM>>>(out, 3);       // output projection
}

// round 4
// speedup vs baseline: 3.1870x; 1.5605x over previous
#include <cuda_runtime.h>
#include <cuda_bf16.h>
#include <math_constants.h>
#include <cstdint>

// Problem constants
#define S_LEN   2048
#define DMODEL  2048
#define NHEADS  16
#define HDIM    128
#define BATCH   4
#define MROWS   (BATCH * S_LEN)   // 8192

// ---------------------------------------------------------------------------
// Scratch (device globals; no allocation in kernel_launch)
// ---------------------------------------------------------------------------
__device__ __nv_bfloat16 g_xhi[(size_t)MROWS * DMODEL];
__device__ __nv_bfloat16 g_xlo[(size_t)MROWS * DMODEL];
__device__ __nv_bfloat16 g_whi[4][(size_t)DMODEL * DMODEL];
__device__ __nv_bfloat16 g_wlo[4][(size_t)DMODEL * DMODEL];
__device__ float g_q[(size_t)BATCH * NHEADS * S_LEN * HDIM];   // [B,H,S,hd] pre-RoPE
__device__ float g_k[(size_t)BATCH * NHEADS * S_LEN * HDIM];
__device__ __nv_bfloat16 g_qhi[(size_t)BATCH * NHEADS * S_LEN * HDIM];
__device__ __nv_bfloat16 g_qlo[(size_t)BATCH * NHEADS * S_LEN * HDIM];
__device__ __nv_bfloat16 g_khi[(size_t)BATCH * NHEADS * S_LEN * HDIM];
__device__ __nv_bfloat16 g_klo[(size_t)BATCH * NHEADS * S_LEN * HDIM];
__device__ __nv_bfloat16 g_vhi[(size_t)BATCH * NHEADS * S_LEN * HDIM];
__device__ __nv_bfloat16 g_vlo[(size_t)BATCH * NHEADS * S_LEN * HDIM];
__device__ __nv_bfloat16 g_atthi[(size_t)MROWS * DMODEL];      // [B,S,D]
__device__ __nv_bfloat16 g_attlo[(size_t)MROWS * DMODEL];
__device__ float g_ct[64 * S_LEN];                              // cos[d][s]
__device__ float g_st[64 * S_LEN];                              // sin[d][s]

// ---------------------------------------------------------------------------
// PTX helpers (baseline features only)
// ---------------------------------------------------------------------------
__device__ __forceinline__ void cp16(uint32_t smem_dst, const void* gptr) {
    asm volatile("cp.async.cg.shared.global [%0], [%1], 16;"
                 :: "r"(smem_dst), "l"(__cvta_generic_to_global(gptr)) : "memory");
}
__device__ __forceinline__ void cp_commit() {
    asm volatile("cp.async.commit_group;" ::: "memory");
}
template <int N>
__device__ __forceinline__ void cp_wait() {
    asm volatile("cp.async.wait_group %0;" :: "n"(N) : "memory");
}
__device__ __forceinline__ void ldsm4(uint32_t addr, uint32_t r[4]) {
    asm volatile("ldmatrix.sync.aligned.m8n8.x4.shared.b16 {%0,%1,%2,%3}, [%4];"
                 : "=r"(r[0]), "=r"(r[1]), "=r"(r[2]), "=r"(r[3]) : "r"(addr));
}
__device__ __forceinline__ void ldsm4t(uint32_t addr, uint32_t r[4]) {
    asm volatile("ldmatrix.sync.aligned.m8n8.x4.trans.shared.b16 {%0,%1,%2,%3}, [%4];"
                 : "=r"(r[0]), "=r"(r[1]), "=r"(r[2]), "=r"(r[3]) : "r"(addr));
}
__device__ __forceinline__ void mma16816(float c[4], const uint32_t a[4],
                                         const uint32_t b0, const uint32_t b1) {
    asm volatile(
        "mma.sync.aligned.m16n8k16.row.col.f32.bf16.bf16.f32 "
        "{%0,%1,%2,%3}, {%4,%5,%6,%7}, {%8,%9}, {%0,%1,%2,%3};"
        : "+f"(c[0]), "+f"(c[1]), "+f"(c[2]), "+f"(c[3])
        : "r"(a[0]), "r"(a[1]), "r"(a[2]), "r"(a[3]), "r"(b0), "r"(b1));
}
__device__ __forceinline__ uint32_t pack_bf16x2(float x, float y) {
    __nv_bfloat162 t = __halves2bfloat162(__float2bfloat16(x), __float2bfloat16(y));
    return *reinterpret_cast<uint32_t*>(&t);
}

// ---------------------------------------------------------------------------
// Split fp32 -> bf16 (hi, lo).  which: 0 = x, 1..4 = Wq,Wk,Wv,Wo
// ---------------------------------------------------------------------------
__global__ void split_kernel(const float4* __restrict__ src, int which, int n4)
{
    __nv_bfloat16 *hi, *lo;
    if (which == 0) { hi = g_xhi; lo = g_xlo; }
    else            { hi = g_whi[which - 1]; lo = g_wlo[which - 1]; }

    for (int i = blockIdx.x * blockDim.x + threadIdx.x; i < n4;
         i += gridDim.x * blockDim.x) {
        float4 v = src[i];
        float f[4] = {v.x, v.y, v.z, v.w};
        __nv_bfloat16 h[4], l[4];
        #pragma unroll
        for (int j = 0; j < 4; j++) {
            h[j] = __float2bfloat16(f[j]);
            l[j] = __float2bfloat16(f[j] - __bfloat162float(h[j]));
        }
        __nv_bfloat162* hp = reinterpret_cast<__nv_bfloat162*>(hi + 4 * (size_t)i);
        __nv_bfloat162* lp = reinterpret_cast<__nv_bfloat162*>(lo + 4 * (size_t)i);
        hp[0] = __halves2bfloat162(h[0], h[1]);
        hp[1] = __halves2bfloat162(h[2], h[3]);
        lp[0] = __halves2bfloat162(l[0], l[1]);
        lp[1] = __halves2bfloat162(l[2], l[3]);
    }
}

// ---------------------------------------------------------------------------
// RoPE cos/sin tables: g_ct[d*2048+s], d in [0,64)
// ---------------------------------------------------------------------------
__global__ void rope_tab_kernel()
{
    int i = blockIdx.x * blockDim.x + threadIdx.x;
    if (i >= 64 * S_LEN) return;
    int d = i >> 11, s = i & 2047;
    float invf = (float)exp2(-(double)d * 0.20762050593045952);  // log2(1e4)/64
    float th = (float)s * invf;
    float c, sn;
    sincosf(th, &sn, &c);
    g_ct[i] = c;
    g_st[i] = sn;
}

// ---------------------------------------------------------------------------
// RoPE over g_q, g_k -> bf16 hi/lo  ([B,H,S,hd], pair (d, d+64))
// ---------------------------------------------------------------------------
__global__ void rope_apply_kernel()
{
    const int total = BATCH * NHEADS * S_LEN * 64;
    int i = blockIdx.x * blockDim.x + threadIdx.x;
    if (i >= total) return;
    int d = i & 63;
    int rs = i >> 6;            // flat (b,h,s)
    int s = rs & 2047;
    size_t base = (size_t)rs * HDIM;
    float c  = g_ct[d * S_LEN + s];
    float sn = g_st[d * S_LEN + s];

    float qlo = g_q[base + d], qhi = g_q[base + d + 64];
    float q0 = qlo * c - qhi * sn;
    float q1 = qhi * c + qlo * sn;
    __nv_bfloat16 h;
    h = __float2bfloat16(q0); g_qhi[base + d] = h;
    g_qlo[base + d] = __float2bfloat16(q0 - __bfloat162float(h));
    h = __float2bfloat16(q1); g_qhi[base + d + 64] = h;
    g_qlo[base + d + 64] = __float2bfloat16(q1 - __bfloat162float(h));

    float klo = g_k[base + d], khi = g_k[base + d + 64];
    float k0 = klo * c - khi * sn;
    float k1 = khi * c + klo * sn;
    h = __float2bfloat16(k0); g_khi[base + d] = h;
    g_klo[base + d] = __float2bfloat16(k0 - __bfloat162float(h));
    h = __float2bfloat16(k1); g_khi[base + d + 64] = h;
    g_klo[base + d + 64] = __float2bfloat16(k1 - __bfloat162float(h));
}

// ---------------------------------------------------------------------------
// HMMA GEMM (as round 3): D[m,n] = sum_k A[m,k]*W[n,k], 3-product bf16 split.
// modes: 0=Q(->g_q fp32) 1=K(->g_k fp32) 2=V(->g_vhi/lo bf16) 3=att@Wo -> Dout
// ---------------------------------------------------------------------------
#define GM_BM 128
#define GM_BN 128
#define GM_BK 64
#define GM_NIT (DMODEL / GM_BK)          // 32
#define GM_ARR 16384
#define GM_STAGE (4 * GM_ARR)
#define GM_SMEM (2 * GM_STAGE)           // 128KB

__device__ __forceinline__ void gm_load_stage(
    uint32_t t0, int kt, int m0, int n0, int tid,
    const __nv_bfloat16* __restrict__ Ah, const __nv_bfloat16* __restrict__ Al,
    const __nv_bfloat16* __restrict__ Bh, const __nv_bfloat16* __restrict__ Bl)
{
    const int k0 = kt * GM_BK;
    #pragma unroll
    for (int i = 0; i < 4; i++) {
        int lin = tid + i * 256;
        int row = lin >> 3, ch = lin & 7;
        uint32_t soff = (uint32_t)(row * 128 + ((ch ^ (row & 7)) << 4));
        size_t ga = (size_t)(m0 + row) * DMODEL + k0 + ch * 8;
        size_t gb = (size_t)(n0 + row) * DMODEL + k0 + ch * 8;
        cp16(t0 + soff,              Ah + ga);
        cp16(t0 + GM_ARR + soff,     Al + ga);
        cp16(t0 + 2 * GM_ARR + soff, Bh + gb);
        cp16(t0 + 3 * GM_ARR + soff, Bl + gb);
    }
}

__global__ __launch_bounds__(256, 1)
void gemm_hmma(float* __restrict__ Dout, int mode)
{
    extern __shared__ char smraw[];
    const uint32_t sbase = (uint32_t)__cvta_generic_to_shared(smraw);
    const int tid  = threadIdx.x;
    const int warp = tid >> 5;
    const int lane = tid & 31;
    const int m0 = blockIdx.y * GM_BM;
    const int n0 = blockIdx.x * GM_BN;

    const __nv_bfloat16 *Ah, *Al;
    if (mode == 3) { Ah = g_atthi; Al = g_attlo; }
    else           { Ah = g_xhi;   Al = g_xlo; }
    const __nv_bfloat16* Bh = g_whi[mode];
    const __nv_bfloat16* Bl = g_wlo[mode];

    const int wm = warp & 1;
    const int wn = warp >> 1;
    const int quad = lane >> 3;
    const int lr   = lane & 7;

    int arow[4], brow[2];
    #pragma unroll
    for (int i = 0; i < 4; i++) arow[i] = wm * 64 + i * 16 + (quad & 1) * 8 + lr;
    const int aqp = quad >> 1;
    #pragma unroll
    for (int j = 0; j < 2; j++) brow[j] = wn * 32 + j * 16 + (quad >> 1) * 8 + lr;
    const int bqp = quad & 1;

    float c[4][4][4];
    #pragma unroll
    for (int i = 0; i < 4; i++)
        #pragma unroll
        for (int j = 0; j < 4; j++)
            #pragma unroll
            for (int e = 0; e < 4; e++) c[i][j][e] = 0.f;

    gm_load_stage(sbase, 0, m0, n0, tid, Ah, Al, Bh, Bl);
    cp_commit();

    #pragma unroll 1
    for (int kt = 0; kt < GM_NIT; kt++) {
        if (kt + 1 < GM_NIT) {
            gm_load_stage(sbase + ((kt + 1) & 1) * GM_STAGE, kt + 1, m0, n0, tid,
                          Ah, Al, Bh, Bl);
            cp_commit();
            cp_wait<1>();
        } else {
            cp_wait<0>();
        }
        __syncthreads();

        const uint32_t t0 = sbase + (kt & 1) * GM_STAGE;
        #pragma unroll
        for (int s = 0; s < 4; s++) {
            uint32_t ah[4][4], al[4][4];
            #pragma unroll
            for (int i = 0; i < 4; i++) {
                uint32_t off = (uint32_t)(arow[i] * 128 +
                               (((s * 2 + aqp) ^ (arow[i] & 7)) << 4));
                ldsm4(t0 + off,          ah[i]);
                ldsm4(t0 + GM_ARR + off, al[i]);
            }
            uint32_t bh[4][2], bl[4][2];
            #pragma unroll
            for (int j2 = 0; j2 < 2; j2++) {
                uint32_t off = (uint32_t)(brow[j2] * 128 +
                               (((s * 2 + bqp) ^ (brow[j2] & 7)) << 4));
                uint32_t t[4];
                ldsm4(t0 + 2 * GM_ARR + off, t);
                bh[2*j2][0] = t[0]; bh[2*j2][1] = t[1];
                bh[2*j2+1][0] = t[2]; bh[2*j2+1][1] = t[3];
                ldsm4(t0 + 3 * GM_ARR + off, t);
                bl[2*j2][0] = t[0]; bl[2*j2][1] = t[1];
                bl[2*j2+1][0] = t[2]; bl[2*j2+1][1] = t[3];
            }
            #pragma unroll
            for (int i = 0; i < 4; i++)
                #pragma unroll
                for (int j = 0; j < 4; j++) {
                    mma16816(c[i][j], ah[i], bh[j][0], bh[j][1]);
                    mma16816(c[i][j], al[i], bh[j][0], bh[j][1]);
                    mma16816(c[i][j], ah[i], bl[j][0], bl[j][1]);
                }
        }
        __syncthreads();
    }

    // ---------------- epilogue ----------------
    const int h = n0 >> 7;

    #pragma unroll
    for (int i = 0; i < 4; i++) {
        int r0 = m0 + wm * 64 + i * 16 + (lane >> 2);
        #pragma unroll
        for (int half = 0; half < 2; half++) {
            int r = r0 + half * 8;
            #pragma unroll
            for (int j = 0; j < 4; j++) {
                int d = wn * 32 + j * 8 + (lane & 3) * 2;
                float2 v2 = make_float2(c[i][j][half * 2], c[i][j][half * 2 + 1]);
                if (mode <= 1) {
                    float* outp = (mode == 0) ? g_q : g_k;
                    int bb = r >> 11, ss = r & 2047;
                    size_t base = (((size_t)bb * NHEADS + h) * S_LEN + ss) * HDIM + d;
                    *(float2*)(outp + base) = v2;
                } else if (mode == 2) {
                    int bb = r >> 11, ss = r & 2047;
                    size_t base = (((size_t)bb * NHEADS + h) * S_LEN + ss) * HDIM + d;
                    __nv_bfloat16 h0 = __float2bfloat16(v2.x);
                    __nv_bfloat16 h1 = __float2bfloat16(v2.y);
                    *(__nv_bfloat162*)(g_vhi + base) = __halves2bfloat162(h0, h1);
                    *(__nv_bfloat162*)(g_vlo + base) = __halves2bfloat162(
                        __float2bfloat16(v2.x - __bfloat162float(h0)),
                        __float2bfloat16(v2.y - __bfloat162float(h1)));
                } else {
                    *(float2*)(Dout + (size_t)r * DMODEL + n0 + d) = v2;
                }
            }
        }
    }
}

// ---------------------------------------------------------------------------
// HMMA flash attention (causal). CTA = 128 q rows x 64-key tiles, 8 warps,
// warp = 16 q rows x all 64 keys. P kept in registers. 3-product splits.
// smem: Qhi 32K | Qlo 32K | 2 stages x (Khi 16K | Klo 16K | Vhi 16K | Vlo 16K)
// ---------------------------------------------------------------------------
#define FQHI 0
#define FQLO 32768
#define FSTG(s) (65536 + (s) * 65536)
#define FKHI 0
#define FKLO 16384
#define FVHI 32768
#define FVLO 49152
#define FA_SMEM (65536 + 2 * 65536)   // 192KB

__device__ __forceinline__ uint32_t fswz(int row, int ch) {
    return (uint32_t)(row * 256 + ((ch >> 3) << 7) + (((ch & 7) ^ (row & 7)) << 4));
}

__global__ __launch_bounds__(256, 1)
void flash_hmma()
{
    extern __shared__ char smraw[];
    const uint32_t sb = (uint32_t)__cvta_generic_to_shared(smraw);
    const int tid  = threadIdx.x;
    const int w    = tid >> 5;
    const int lane = tid & 31;
    const int quad = lane >> 3;
    const int lr   = lane & 7;
    const int qt = 15 - blockIdx.x;        // heavy CTAs first
    const int bh = blockIdx.y;

    const __nv_bfloat16* qhib = g_qhi + (size_t)bh * S_LEN * HDIM;
    const __nv_bfloat16* qlob = g_qlo + (size_t)bh * S_LEN * HDIM;
    const __nv_bfloat16* khib = g_khi + (size_t)bh * S_LEN * HDIM;
    const __nv_bfloat16* klob = g_klo + (size_t)bh * S_LEN * HDIM;
    const __nv_bfloat16* vhib = g_vhi + (size_t)bh * S_LEN * HDIM;
    const __nv_bfloat16* vlob = g_vlo + (size_t)bh * S_LEN * HDIM;

    // Q tile loads (128 rows x 16 chunks, hi+lo)
    #pragma unroll
    for (int i = 0; i < 8; i++) {
        int lin = tid + i * 256;
        int row = lin >> 4, ch = lin & 15;
        uint32_t so = fswz(row, ch);
        size_t go = (size_t)(qt * 128 + row) * HDIM + ch * 8;
        cp16(sb + FQHI + so, qhib + go);
        cp16(sb + FQLO + so, qlob + go);
    }
    cp_commit();

    const int nkt = 2 * qt + 2;

    // KV stage 0
    {
        const uint32_t t0 = sb + FSTG(0);
        #pragma unroll
        for (int i = 0; i < 4; i++) {
            int lin = tid + i * 256;
            int row = lin >> 4, ch = lin & 15;
            uint32_t so = fswz(row, ch);
            size_t go = (size_t)row * HDIM + ch * 8;
            cp16(t0 + FKHI + so, khib + go);
            cp16(t0 + FKLO + so, klob + go);
            cp16(t0 + FVHI + so, vhib + go);
            cp16(t0 + FVLO + so, vlob + go);
        }
        cp_commit();
    }

    float o[16][4];
    #pragma unroll
    for (int i = 0; i < 16; i++)
        #pragma unroll
        for (int e = 0; e < 4; e++) o[i][e] = 0.f;
    float mi[2] = {-CUDART_INF_F, -CUDART_INF_F};
    float li[2] = {0.f, 0.f};

    const float scale = 0.08838834764831845f;   // 1/sqrt(128)
    const int ar  = 16 * w + (quad & 1) * 8 + lr;   // A ldsm row
    const int aqp = quad >> 1;
    const int krb = (quad >> 1) * 8 + lr;            // K ldsm row base
    const int bqp = quad & 1;
    const int vrb = (quad & 1) * 8 + lr;             // V ldsm row base
    const int vqp = quad >> 1;

    #pragma unroll 1
    for (int kt = 0; kt < nkt; kt++) {
        if (kt + 1 < nkt) {
            const uint32_t t0 = sb + FSTG((kt + 1) & 1);
            #pragma unroll
            for (int i = 0; i < 4; i++) {
                int lin = tid + i * 256;
                int row = lin >> 4, ch = lin & 15;
                uint32_t so = fswz(row, ch);
                size_t go = (size_t)((kt + 1) * 64 + row) * HDIM + ch * 8;
                cp16(t0 + FKHI + so, khib + go);
                cp16(t0 + FKLO + so, klob + go);
                cp16(t0 + FVHI + so, vhib + go);
                cp16(t0 + FVLO + so, vlob + go);
            }
            cp_commit();
            cp_wait<1>();
        } else {
            cp_wait<0>();
        }
        __syncthreads();

        const uint32_t stg = sb + FSTG(kt & 1);

        // ---- QK^T: sc[8 n-tiles][4] ----
        float sc[8][4];
        #pragma unroll
        for (int i = 0; i < 8; i++)
            #pragma unroll
            for (int e = 0; e < 4; e++) sc[i][e] = 0.f;

        #pragma unroll
        for (int s = 0; s < 8; s++) {
            uint32_t qh[4], ql[4];
            uint32_t ao = fswz(ar, s * 2 + aqp);
            ldsm4(sb + FQHI + ao, qh);
            ldsm4(sb + FQLO + ao, ql);
            #pragma unroll
            for (int j2 = 0; j2 < 4; j2++) {
                uint32_t bo = fswz(j2 * 16 + krb, s * 2 + bqp);
                uint32_t th[4], tl[4];
                ldsm4(stg + FKHI + bo, th);
                ldsm4(stg + FKLO + bo, tl);
                mma16816(sc[2*j2],   qh, th[0], th[1]);
                mma16816(sc[2*j2],   ql, th[0], th[1]);
                mma16816(sc[2*j2],   qh, tl[0], tl[1]);
                mma16816(sc[2*j2+1], qh, th[2], th[3]);
                mma16816(sc[2*j2+1], ql, th[2], th[3]);
                mma16816(sc[2*j2+1], qh, tl[2], tl[3]);
            }
        }

        // ---- online softmax (rows ra = half 0, rb = half 1) ----
        const bool needmask = (kt * 64 + 63 > qt * 128 + 16 * w);
        const int rbase = qt * 128 + 16 * w + (lane >> 2);
        #pragma unroll
        for (int half = 0; half < 2; half++) {
            const int rg = rbase + half * 8;
            float mx = -CUDART_INF_F;
            #pragma unroll
            for (int dj = 0; dj < 8; dj++) {
                #pragma unroll
                for (int e = 0; e < 2; e++) {
                    float v = sc[dj][half * 2 + e] * scale;
                    if (needmask) {
                        int col = kt * 64 + dj * 8 + (lane & 3) * 2 + e;
                        if (col > rg) v = -CUDART_INF_F;
                    }
                    sc[dj][half * 2 + e] = v;
                    mx = fmaxf(mx, v);
                }
            }
            mx = fmaxf(mx, __shfl_xor_sync(0xffffffffu, mx, 1));
            mx = fmaxf(mx, __shfl_xor_sync(0xffffffffu, mx, 2));
            float mnew = fmaxf(mi[half], mx);
            float fct  = __expf(mi[half] - mnew);
            mi[half] = mnew;
            float ssum = 0.f;
            #pragma unroll
            for (int dj = 0; dj < 8; dj++) {
                #pragma unroll
                for (int e = 0; e < 2; e++) {
                    float p = __expf(sc[dj][half * 2 + e] - mnew);
                    sc[dj][half * 2 + e] = p;
                    ssum += p;
                }
            }
            ssum += __shfl_xor_sync(0xffffffffu, ssum, 1);
            ssum += __shfl_xor_sync(0xffffffffu, ssum, 2);
            li[half] = li[half] * fct + ssum;
            #pragma unroll
            for (int dt = 0; dt < 16; dt++) {
                o[dt][half * 2]     *= fct;
                o[dt][half * 2 + 1] *= fct;
            }
        }

        // ---- PV: o[16 d-tiles][4] += P @ V ----
        #pragma unroll
        for (int t = 0; t < 4; t++) {
            uint32_t ph[4], pl[4];
            #pragma unroll
            for (int pair = 0; pair < 2; pair++) {
                const float* sp = sc[2 * t + pair];
                #pragma unroll
                for (int hh = 0; hh < 2; hh++) {
                    float p0 = sp[hh * 2], p1 = sp[hh * 2 + 1];
                    uint32_t hi = pack_bf16x2(p0, p1);
                    __nv_bfloat162 hb = *reinterpret_cast<__nv_bfloat162*>(&hi);
                    uint32_t lo = pack_bf16x2(p0 - __bfloat162float(hb.x),
                                              p1 - __bfloat162float(hb.y));
                    ph[pair * 2 + hh] = hi;
                    pl[pair * 2 + hh] = lo;
                }
            }
            #pragma unroll
            for (int j2 = 0; j2 < 8; j2++) {
                uint32_t vo = fswz(t * 16 + vrb, j2 * 2 + vqp);
                uint32_t vh[4], vl[4];
                ldsm4t(stg + FVHI + vo, vh);
                ldsm4t(stg + FVLO + vo, vl);
                mma16816(o[2*j2],   ph, vh[0], vh[1]);
                mma16816(o[2*j2],   pl, vh[0], vh[1]);
                mma16816(o[2*j2],   ph, vl[0], vl[1]);
                mma16816(o[2*j2+1], ph, vh[2], vh[3]);
                mma16816(o[2*j2+1], pl, vh[2], vh[3]);
                mma16816(o[2*j2+1], ph, vl[2], vl[3]);
            }
        }
        __syncthreads();
    }

    // ---- epilogue: normalize, split bf16, write att [B,S,D] ----
    const int b  = bh >> 4;
    const int hh = bh & 15;
    const float inva = 1.0f / li[0];
    const float invb = 1.0f / li[1];
    const int sa = qt * 128 + 16 * w + (lane >> 2);

    #pragma unroll
    for (int dj = 0; dj < 16; dj++) {
        int col = hh * HDIM + dj * 8 + (lane & 3) * 2;
        size_t ia = ((size_t)b * S_LEN + sa) * DMODEL + col;
        size_t ib = ((size_t)b * S_LEN + sa + 8) * DMODEL + col;
        float a0 = o[dj][0] * inva, a1 = o[dj][1] * inva;
        float b0 = o[dj][2] * invb, b1 = o[dj][3] * invb;
        __nv_bfloat16 ha0 = __float2bfloat16(a0), ha1 = __float2bfloat16(a1);
        __nv_bfloat16 hb0 = __float2bfloat16(b0), hb1 = __float2bfloat16(b1);
        *(__nv_bfloat162*)(g_atthi + ia) = __halves2bfloat162(ha0, ha1);
        *(__nv_bfloat162*)(g_attlo + ia) = __halves2bfloat162(
            __float2bfloat16(a0 - __bfloat162float(ha0)),
            __float2bfloat16(a1 - __bfloat162float(ha1)));
        *(__nv_bfloat162*)(g_atthi + ib) = __halves2bfloat162(hb0, hb1);
        *(__nv_bfloat162*)(g_attlo + ib) = __halves2bfloat162(
            __float2bfloat16(b0 - __bfloat162float(hb0)),
            __float2bfloat16(b1 - __bfloat162float(hb1)));
    }
}

// ---------------------------------------------------------------------------
// Launch
// ---------------------------------------------------------------------------
extern "C" void kernel_launch(void* const* d_in, const int* in_sizes, int n_in,
                              void* d_out, int out_size)
{
    const float* x  = (const float*)d_in[0];
    const float* Wq = (const float*)d_in[1];
    const float* Wk = (const float*)d_in[2];
    const float* Wv = (const float*)d_in[3];
    const float* Wo = (const float*)d_in[4];
    float* out = (float*)d_out;

    int n4x = MROWS * DMODEL / 4;
    int n4w = DMODEL * DMODEL / 4;
    split_kernel<<<2048, 256>>>((const float4*)x,  0, n4x);
    split_kernel<<<1024, 256>>>((const float4*)Wq, 1, n4w);
    split_kernel<<<1024, 256>>>((const float4*)Wk, 2, n4w);
    split_kernel<<<1024, 256>>>((const float4*)Wv, 3, n4w);
    split_kernel<<<1024, 256>>>((const float4*)Wo, 4, n4w);
    rope_tab_kernel<<<(64 * S_LEN + 255) / 256, 256>>>();

    cudaFuncSetAttribute(gemm_hmma, cudaFuncAttributeMaxDynamicSharedMemorySize, GM_SMEM);
    dim3 gblk(DMODEL / GM_BN, MROWS / GM_BM);   // 16 x 64

    gemm_hmma<<<gblk, 256, GM_SMEM>>>(nullptr, 0);   // Q (fp32, pre-RoPE)
    gemm_hmma<<<gblk, 256, GM_SMEM>>>(nullptr, 1);   // K (fp32, pre-RoPE)
    gemm_hmma<<<gblk, 256, GM_SMEM>>>(nullptr, 2);   // V (bf16 hi/lo)

    rope_apply_kernel<<<(BATCH * NHEADS * S_LEN * 64 + 255) / 256, 256>>>();

    cudaFuncSetAttribute(flash_hmma, cudaFuncAttributeMaxDynamicSharedMemorySize, FA_SMEM);
    flash_hmma<<<dim3(16, BATCH * NHEADS), 256, FA_SMEM>>>();

    gemm_hmma<<<gblk, 256, GM_SMEM>>>(out, 3);       // output projection
}